// round 14
// baseline (speedup 1.0000x reference)
#include <cuda_runtime.h>
#include <cuda_fp16.h>
#include <cstdint>

// ---------------------------------------------------------------------------
// Tri-plane sampling, channel-last fp16 scratch, PLANE-PIPELINED:
//   default: t2a -> t2b -> t2c -> t0 -> t1   (biggest transposes first)
//   stream B: s2a(after t2a) -> s2b(after t2b) -> s2c(after t2c)
//   stream C: s0(after t0)
//   stream D: s1(after t1)
//   so the large level-2 sampling starts ~10us into the graph instead of ~41.
// ---------------------------------------------------------------------------

#define TOTAL_PX 1032192u   // 3*128^2 + 3*256^2 + 3*512^2
// 4 uint4 per pixel (32 x fp16); +4 pad for the x-edge row-pair overread
__device__ uint4 g_buf[TOTAL_PX * 4 + 4];   // 66 MB, 16B-aligned

__constant__ unsigned c_base_px[9] = {0u,      16384u,  32768u,
                                      49152u,  114688u, 180224u,
                                      245760u, 507904u, 770048u};
__constant__ int      c_npix[9]    = {16384, 16384, 16384,
                                      65536, 65536, 65536,
                                      262144, 262144, 262144};
// tile_start[i] = base_px[i] / 128  (128 pixels per block)
__constant__ int      c_tile_start[9] = {0, 128, 256,
                                         384, 896, 1408,
                                         1920, 3968, 6016};

struct GridPtrs { const float* g[9]; };

__global__ void __launch_bounds__(256)
transpose_part(GridPtrs ptrs, int tile_bias) {
    __shared__ float tile[128][33];   // stride 33: conflict-free both phases
    const int b = blockIdx.x + tile_bias;

    int gi = 0;
    #pragma unroll
    for (int i = 1; i < 9; i++)
        if (b >= c_tile_start[i]) gi = i;

    const float* __restrict__ g = ptrs.g[gi];
    const int npix = c_npix[gi];
    const int pix0 = (b - c_tile_start[gi]) * 128;

    const int tx = threadIdx.x & 31;
    const int ty = threadIdx.x >> 5;   // warp id 0..7

    #pragma unroll
    for (int c = ty; c < 32; c += 8) {
        const float* row = g + (size_t)c * npix + pix0;
        #pragma unroll
        for (int j = 0; j < 4; j++)
            tile[32 * j + tx][c] = __ldcs(row + 32 * j + tx);  // evict-first
    }
    __syncthreads();

    __half2* dst = (__half2*)g_buf + ((size_t)c_base_px[gi] + pix0) * 16;
    const int hl = tx & 15;
    #pragma unroll
    for (int s = 0; s < 8; s++) {
        const int pix = ty * 16 + s * 2 + (tx >> 4);
        const float a  = tile[pix][2 * hl];
        const float c2 = tile[pix][2 * hl + 1];
        dst[(size_t)pix * 16 + hl] = __floats2half2_rn(a, c2);
    }
}

// ---- shared sampler core: sample one plane, write 128B output line ----
// PLANE selects (W,H) coords: 0 -> (py,pz), 1 -> (px,pz), 2 -> (px,py)
template <int R, unsigned B0, int PLANE>
__device__ __forceinline__ void sample_one_plane(
    float px, float py, float pz, int s, bool isR, bool live, float* outp) {

    const float w = (PLANE == 0) ? py : px;
    const float h = (PLANE == 2) ? py : pz;
    const float Rm1 = (float)(R - 1);

    float x = (w + 1.0f) * 0.5f * Rm1;
    x = fminf(fmaxf(x, 0.0f), Rm1);
    float y = (h + 1.0f) * 0.5f * Rm1;
    y = fminf(fmaxf(y, 0.0f), Rm1);

    const float x0f = floorf(x), y0f = floorf(y);
    const float wx = x - x0f,    wy = y - y0f;
    const int x0 = (int)x0f,     y0 = (int)y0f;
    const int y1 = min(y0 + 1, R - 1);
    // x1 implicit: the 128B row-pair covers x0 and x0+1; at x0==R-1,
    // wx==0 so the (padded, in-bounds) overread has zero weight.

    const __half2 wy2  = __float2half2_rn(wy);
    const __half2 iwy2 = __float2half2_rn(1.0f - wy);
    const __half2 wx2  = __float2half2_rn(wx);
    const __half2 iwx2 = __float2half2_rn(1.0f - wx);

    const uint4* base = g_buf + ((size_t)B0 << 2) + s;
    const uint4 a = __ldg(base + ((size_t)(y0 * R + x0) << 2));  // row y0
    const uint4 b = __ldg(base + ((size_t)(y1 * R + x0) << 2));  // row y1

    unsigned int ry[4];
    #pragma unroll
    for (int k = 0; k < 4; k++) {
        const unsigned int ua = (&a.x)[k], ub = (&b.x)[k];
        const __half2 v = __hfma2(*(const __half2*)&ub, wy2,
                                  __hmul2(*(const __half2*)&ua, iwy2));
        ry[k] = *(const unsigned int*)&v;
    }

    unsigned int res[4];
    #pragma unroll
    for (int k = 0; k < 4; k++) {
        const unsigned int o = __shfl_xor_sync(0xffffffffu, ry[k], 4);
        const unsigned int ulo = isR ? o     : ry[k];   // x0 corner
        const unsigned int uhi = isR ? ry[k] : o;       // x1 corner
        const __half2 v = __hfma2(*(const __half2*)&uhi, wx2,
                                  __hmul2(*(const __half2*)&ulo, iwx2));
        res[k] = *(const unsigned int*)&v;
    }

    if (live) {
        const unsigned int w0 = isR ? res[2] : res[0];
        const unsigned int w1 = isR ? res[3] : res[1];
        const float2 f0 = __half22float2(*(const __half2*)&w0);
        const float2 f1 = __half22float2(*(const __half2*)&w1);
        float4 v; v.x = f0.x; v.y = f0.y; v.z = f1.x; v.w = f1.y;
        __stcs((float4*)outp, v);   // streaming output store
    }
}

// common per-thread prologue
#define SAMPLE_PROLOGUE                                                     \
    const int warp = (int)((blockIdx.x * 256u + threadIdx.x) >> 5);         \
    const int lane = threadIdx.x & 31;                                      \
    const int s    = lane & 7;                                              \
    const int pt   = warp * 4 + (lane >> 3);                                \
    const int ptc  = min(pt, n - 1);                                        \
    const bool live = (pt < n);                                             \
    const float vx = __ldg(pts + 3 * (size_t)ptc + 0);                      \
    const float vy = __ldg(pts + 3 * (size_t)ptc + 1);                      \
    const float vz = __ldg(pts + 3 * (size_t)ptc + 2);                      \
    const float px = (vx - 1.6f) * (-0.625f) - 1.0f;                        \
    const float py = (vy - 1.6f) * (-0.625f) - 1.0f;                        \
    const float pz = (vz - 1.6f) * (-0.625f) - 1.0f;                        \
    const bool isR = (s >= 4);                                              \
    float* outp = out + (size_t)ptc * 288 + 8 * (s & 3) + 4 * (s >> 2);

// 3-plane sampler for levels 0/1 (LIDX in {0,1})
template <int LIDX, int R, unsigned B0>
__global__ void __launch_bounds__(256)
sample_level(const float* __restrict__ pts, float* __restrict__ out, int n) {
    SAMPLE_PROLOGUE
    sample_one_plane<R, B0,                      0>(px, py, pz, s, isR, live,
                                                    outp + LIDX * 96 + 0);
    sample_one_plane<R, B0 + (unsigned)R * R,    1>(px, py, pz, s, isR, live,
                                                    outp + LIDX * 96 + 32);
    sample_one_plane<R, B0 + 2u * (unsigned)R * R, 2>(px, py, pz, s, isR, live,
                                                    outp + LIDX * 96 + 64);
}

// single-plane sampler for level 2 (plane PLANE)
template <int PLANE>
__global__ void __launch_bounds__(256)
sample_l2_plane(const float* __restrict__ pts, float* __restrict__ out, int n) {
    SAMPLE_PROLOGUE
    sample_one_plane<512, 245760u + (unsigned)PLANE * 262144u, PLANE>(
        px, py, pz, s, isR, live, outp + 192 + PLANE * 32);
}

extern "C" void kernel_launch(void* const* d_in, const int* in_sizes, int n_in,
                              void* d_out, int out_size) {
    const float* pts = (const float*)d_in[0];
    float* out = (float*)d_out;
    const int n = in_sizes[0] / 3;  // 300000 points

    GridPtrs ptrs;
    for (int i = 0; i < 9; i++) ptrs.g[i] = (const float*)d_in[1 + i];

    // one-time creation of side streams + events (resources, not work)
    static cudaStream_t sB = nullptr, sC = nullptr, sD = nullptr;
    static cudaEvent_t  e2a, e2b, e2c, e0, e1, jB, jC, jD;
    if (sB == nullptr) {
        cudaStreamCreateWithFlags(&sB, cudaStreamNonBlocking);
        cudaStreamCreateWithFlags(&sC, cudaStreamNonBlocking);
        cudaStreamCreateWithFlags(&sD, cudaStreamNonBlocking);
        cudaEventCreateWithFlags(&e2a, cudaEventDisableTiming);
        cudaEventCreateWithFlags(&e2b, cudaEventDisableTiming);
        cudaEventCreateWithFlags(&e2c, cudaEventDisableTiming);
        cudaEventCreateWithFlags(&e0,  cudaEventDisableTiming);
        cudaEventCreateWithFlags(&e1,  cudaEventDisableTiming);
        cudaEventCreateWithFlags(&jB,  cudaEventDisableTiming);
        cudaEventCreateWithFlags(&jC,  cudaEventDisableTiming);
        cudaEventCreateWithFlags(&jD,  cudaEventDisableTiming);
    }

    const int sblocks = (n + 31) / 32;   // 4 pts/warp, 8 warps/block

    // default stream: biggest transposes first (level-2 per-plane), then 0,1
    transpose_part<<<2048, 256>>>(ptrs, 1920);   // plane 6 (l2,p0)
    cudaEventRecord(e2a, 0);
    transpose_part<<<2048, 256>>>(ptrs, 3968);   // plane 7 (l2,p1)
    cudaEventRecord(e2b, 0);
    transpose_part<<<2048, 256>>>(ptrs, 6016);   // plane 8 (l2,p2)
    cudaEventRecord(e2c, 0);
    transpose_part<<<384,  256>>>(ptrs, 0);      // level 0 (all 3 planes)
    cudaEventRecord(e0, 0);
    transpose_part<<<1536, 256>>>(ptrs, 384);    // level 1 (all 3 planes)
    cudaEventRecord(e1, 0);

    // stream B: level-2 samplers, plane by plane
    cudaStreamWaitEvent(sB, e2a, 0);
    sample_l2_plane<0><<<sblocks, 256, 0, sB>>>(pts, out, n);
    cudaStreamWaitEvent(sB, e2b, 0);
    sample_l2_plane<1><<<sblocks, 256, 0, sB>>>(pts, out, n);
    cudaStreamWaitEvent(sB, e2c, 0);
    sample_l2_plane<2><<<sblocks, 256, 0, sB>>>(pts, out, n);

    // stream C: level-0 sampler
    cudaStreamWaitEvent(sC, e0, 0);
    sample_level<0, 128, 0u><<<sblocks, 256, 0, sC>>>(pts, out, n);

    // stream D: level-1 sampler
    cudaStreamWaitEvent(sD, e1, 0);
    sample_level<1, 256, 49152u><<<sblocks, 256, 0, sD>>>(pts, out, n);

    // join all side streams back into the capture (default) stream
    cudaEventRecord(jB, sB);
    cudaEventRecord(jC, sC);
    cudaEventRecord(jD, sD);
    cudaStreamWaitEvent(0, jB, 0);
    cudaStreamWaitEvent(0, jC, 0);
    cudaStreamWaitEvent(0, jD, 0);
}